// round 1
// baseline (speedup 1.0000x reference)
#include <cuda_runtime.h>
#include <math.h>

// Problem dims
#define DIM     768
#define HEADS   12
#define HD      64
#define HIDDEN  3072
#define SEQ     1024
#define BATCHN  8
#define TOK     (BATCHN*SEQ)   // 8192
#define QKVDIM  (3*DIM)        // 2304
#define NBH     (BATCHN*HEADS) // 96

// ---------------- scratch (device globals; no cudaMalloc allowed) ----------------
__device__ float g_h1[TOK*DIM];
__device__ float g_qkv[(size_t)TOK*QKVDIM];
__device__ float g_scores[(size_t)NBH*SEQ*SEQ];   // 402 MB
__device__ float g_olin[TOK*DIM];
__device__ float g_x2[TOK*DIM];
__device__ float g_h2[TOK*DIM];
__device__ float g_h3[(size_t)TOK*HIDDEN];

// ---------------- LayerNorm: one block (256 thr) per row of 768 ----------------
__global__ void ln_kernel(const float* __restrict__ in,
                          const float* __restrict__ gam,
                          const float* __restrict__ bet,
                          float* __restrict__ out) {
    int row = blockIdx.x;
    int t = threadIdx.x;
    const float* x = in + (size_t)row * DIM;
    float v0 = x[t], v1 = x[t + 256], v2 = x[t + 512];
    float s  = v0 + v1 + v2;
    float sq = v0*v0 + v1*v1 + v2*v2;

    __shared__ float redS[8], redQ[8];
    #pragma unroll
    for (int o = 16; o > 0; o >>= 1) {
        s  += __shfl_xor_sync(0xffffffffu, s,  o);
        sq += __shfl_xor_sync(0xffffffffu, sq, o);
    }
    if ((t & 31) == 0) { redS[t >> 5] = s; redQ[t >> 5] = sq; }
    __syncthreads();
    if (t < 32) {
        float s2 = (t < 8) ? redS[t] : 0.f;
        float q2 = (t < 8) ? redQ[t] : 0.f;
        #pragma unroll
        for (int o = 4; o > 0; o >>= 1) {
            s2 += __shfl_xor_sync(0xffffffffu, s2, o);
            q2 += __shfl_xor_sync(0xffffffffu, q2, o);
        }
        if (t == 0) { redS[0] = s2; redQ[0] = q2; }
    }
    __syncthreads();
    float mu  = redS[0] * (1.0f / DIM);
    float var = redQ[0] * (1.0f / DIM) - mu * mu;
    float inv = rsqrtf(var + 1e-5f);

    float* o = out + (size_t)row * DIM;
    o[t]       = (v0 - mu) * inv * gam[t]       + bet[t];
    o[t + 256] = (v1 - mu) * inv * gam[t + 256] + bet[t + 256];
    o[t + 512] = (v2 - mu) * inv * gam[t + 512] + bet[t + 512];
}

// ---------------- GEMM TN: C[M,N] = A[M,K] * W[N,K]^T, 128x128x8 tiles ----------------
enum { EPI_SCALE = 0, EPI_BIAS = 1, EPI_BIAS_RES = 2, EPI_BIAS_GELU = 3 };

template<int EPI>
__device__ __forceinline__ void gemm_tn_body(
    const float* __restrict__ A, int lda,
    const float* __restrict__ W, int ldw,
    float* __restrict__ C, int ldc,
    int K,
    const float* __restrict__ bias,
    const float* __restrict__ res, int ldres,
    float alpha)
{
    __shared__ float As[8][128];
    __shared__ float Ws[8][128];
    int tid = threadIdx.x;
    int tx = tid & 15, ty = tid >> 4;
    int m0 = blockIdx.y * 128, n0 = blockIdx.x * 128;
    int lr = tid >> 1;           // 0..127 row in tile
    int lk = (tid & 1) * 4;      // 0 or 4
    const float* Aptr = A + (size_t)(m0 + lr) * lda + lk;
    const float* Wptr = W + (size_t)(n0 + lr) * ldw + lk;

    float acc[8][8];
    #pragma unroll
    for (int i = 0; i < 8; i++)
        #pragma unroll
        for (int j = 0; j < 8; j++) acc[i][j] = 0.f;

    for (int k0 = 0; k0 < K; k0 += 8) {
        float4 av = *(const float4*)(Aptr + k0);
        float4 wv = *(const float4*)(Wptr + k0);
        As[lk+0][lr] = av.x; As[lk+1][lr] = av.y; As[lk+2][lr] = av.z; As[lk+3][lr] = av.w;
        Ws[lk+0][lr] = wv.x; Ws[lk+1][lr] = wv.y; Ws[lk+2][lr] = wv.z; Ws[lk+3][lr] = wv.w;
        __syncthreads();
        #pragma unroll
        for (int k = 0; k < 8; k++) {
            float a[8], w[8];
            #pragma unroll
            for (int i = 0; i < 8; i++) a[i] = As[k][ty * 8 + i];
            #pragma unroll
            for (int j = 0; j < 8; j++) w[j] = Ws[k][tx * 8 + j];
            #pragma unroll
            for (int i = 0; i < 8; i++)
                #pragma unroll
                for (int j = 0; j < 8; j++)
                    acc[i][j] = fmaf(a[i], w[j], acc[i][j]);
        }
        __syncthreads();
    }

    #pragma unroll
    for (int i = 0; i < 8; i++) {
        int m = m0 + ty * 8 + i;
        #pragma unroll
        for (int j4 = 0; j4 < 2; j4++) {
            int n = n0 + tx * 8 + j4 * 4;
            float4 v;
            v.x = acc[i][j4*4+0]; v.y = acc[i][j4*4+1];
            v.z = acc[i][j4*4+2]; v.w = acc[i][j4*4+3];
            if (EPI == EPI_SCALE) {
                v.x *= alpha; v.y *= alpha; v.z *= alpha; v.w *= alpha;
            }
            if (EPI >= EPI_BIAS) {
                float4 bb = *(const float4*)(bias + n);
                v.x += bb.x; v.y += bb.y; v.z += bb.z; v.w += bb.w;
            }
            if (EPI == EPI_BIAS_RES) {
                float4 rr = *(const float4*)(res + (size_t)m * ldres + n);
                v.x += rr.x; v.y += rr.y; v.z += rr.z; v.w += rr.w;
            }
            if (EPI == EPI_BIAS_GELU) {
                v.x = 0.5f * v.x * (1.f + erff(v.x * 0.70710678118f));
                v.y = 0.5f * v.y * (1.f + erff(v.y * 0.70710678118f));
                v.z = 0.5f * v.z * (1.f + erff(v.z * 0.70710678118f));
                v.w = 0.5f * v.w * (1.f + erff(v.w * 0.70710678118f));
            }
            *(float4*)(C + (size_t)m * ldc + n) = v;
        }
    }
}

template<int EPI>
__global__ __launch_bounds__(256)
void gemm_tn_kernel(const float* __restrict__ A, int lda,
                    const float* __restrict__ W, int ldw,
                    float* __restrict__ C, int ldc, int K,
                    const float* __restrict__ bias,
                    const float* __restrict__ res, int ldres, float alpha) {
    gemm_tn_body<EPI>(A, lda, W, ldw, C, ldc, K, bias, res, ldres, alpha);
}

// S = (Q @ K^T) * scale per (b,h).  Q,K are strided views into g_qkv.
__global__ __launch_bounds__(256)
void gemm_qk_kernel(const float* __restrict__ qkv, float* __restrict__ scores) {
    int z = blockIdx.z; int b = z / HEADS, h = z % HEADS;
    const float* A = qkv + (size_t)b * SEQ * QKVDIM + h * HD;           // Q
    const float* W = qkv + (size_t)b * SEQ * QKVDIM + DIM + h * HD;     // K
    float* C = scores + (size_t)z * SEQ * SEQ;
    gemm_tn_body<EPI_SCALE>(A, QKVDIM, W, QKVDIM, C, SEQ, HD,
                            nullptr, nullptr, 0, 0.125f);
}

// ---------------- softmax over rows of 1024 (one pass, reg-resident) ----------------
__global__ __launch_bounds__(256)
void softmax_kernel(float* __restrict__ scores) {
    size_t row = blockIdx.x;
    float4* rp = (float4*)(scores + row * SEQ);
    int t = threadIdx.x;
    float4 v = rp[t];
    float mx = fmaxf(fmaxf(v.x, v.y), fmaxf(v.z, v.w));
    __shared__ float redM[8], redS[8];
    #pragma unroll
    for (int o = 16; o > 0; o >>= 1) mx = fmaxf(mx, __shfl_xor_sync(0xffffffffu, mx, o));
    if ((t & 31) == 0) redM[t >> 5] = mx;
    __syncthreads();
    if (t < 32) {
        float m2 = (t < 8) ? redM[t] : -1e30f;
        #pragma unroll
        for (int o = 4; o > 0; o >>= 1) m2 = fmaxf(m2, __shfl_xor_sync(0xffffffffu, m2, o));
        if (t == 0) redM[0] = m2;
    }
    __syncthreads();
    mx = redM[0];
    v.x = expf(v.x - mx); v.y = expf(v.y - mx);
    v.z = expf(v.z - mx); v.w = expf(v.w - mx);
    float s = v.x + v.y + v.z + v.w;
    #pragma unroll
    for (int o = 16; o > 0; o >>= 1) s += __shfl_xor_sync(0xffffffffu, s, o);
    if ((t & 31) == 0) redS[t >> 5] = s;
    __syncthreads();
    if (t < 32) {
        float s2 = (t < 8) ? redS[t] : 0.f;
        #pragma unroll
        for (int o = 4; o > 0; o >>= 1) s2 += __shfl_xor_sync(0xffffffffu, s2, o);
        if (t == 0) redS[0] = s2;
    }
    __syncthreads();
    float inv = 1.f / redS[0];
    v.x *= inv; v.y *= inv; v.z *= inv; v.w *= inv;
    rp[t] = v;
}

// ---------------- O = P @ V  (NN GEMM, 128x64 tiles), scatter to [B,N,H*HD] ----------------
__global__ __launch_bounds__(256)
void gemm_pv_kernel(const float* __restrict__ scores,
                    const float* __restrict__ qkv,
                    float* __restrict__ olin) {
    int z = blockIdx.z; int b = z / HEADS, h = z % HEADS;
    const float* A  = scores + (size_t)z * SEQ * SEQ;                      // [1024,1024]
    const float* Bv = qkv + (size_t)b * SEQ * QKVDIM + 2 * DIM + h * HD;   // V rows (ldb=2304)
    float* C = olin + (size_t)b * SEQ * DIM + h * HD;                      // ldc=768

    __shared__ float As[16][128];
    __shared__ float Bs[16][64];
    int tid = threadIdx.x, tx = tid & 15, ty = tid >> 4;
    int m0 = blockIdx.y * 128;

    float acc[8][4];
    #pragma unroll
    for (int i = 0; i < 8; i++)
        #pragma unroll
        for (int j = 0; j < 4; j++) acc[i][j] = 0.f;

    for (int k0 = 0; k0 < SEQ; k0 += 16) {
        #pragma unroll
        for (int r = 0; r < 2; r++) {
            int f = tid + r * 256;          // float4 index 0..511
            int row = f >> 2, c4 = (f & 3) * 4;
            float4 av = *(const float4*)(A + (size_t)(m0 + row) * SEQ + k0 + c4);
            As[c4+0][row] = av.x; As[c4+1][row] = av.y;
            As[c4+2][row] = av.z; As[c4+3][row] = av.w;
        }
        {
            int krow = tid >> 4;            // 0..15
            int nc = (tid & 15) * 4;        // 0..60
            float4 bv = *(const float4*)(Bv + (size_t)(k0 + krow) * QKVDIM + nc);
            *(float4*)&Bs[krow][nc] = bv;
        }
        __syncthreads();
        #pragma unroll
        for (int k = 0; k < 16; k++) {
            float a[8], bb[4];
            #pragma unroll
            for (int i = 0; i < 8; i++) a[i] = As[k][ty * 8 + i];
            #pragma unroll
            for (int j = 0; j < 4; j++) bb[j] = Bs[k][tx * 4 + j];
            #pragma unroll
            for (int i = 0; i < 8; i++)
                #pragma unroll
                for (int j = 0; j < 4; j++)
                    acc[i][j] = fmaf(a[i], bb[j], acc[i][j]);
        }
        __syncthreads();
    }
    #pragma unroll
    for (int i = 0; i < 8; i++) {
        int m = m0 + ty * 8 + i;
        float4 v; v.x = acc[i][0]; v.y = acc[i][1]; v.z = acc[i][2]; v.w = acc[i][3];
        *(float4*)(C + (size_t)m * DIM + tx * 4) = v;
    }
}

// ---------------- launch ----------------
extern "C" void kernel_launch(void* const* d_in, const int* in_sizes, int n_in,
                              void* d_out, int out_size) {
    const float* x       = (const float*)d_in[0];
    const float* n1g     = (const float*)d_in[1];
    const float* n1b     = (const float*)d_in[2];
    const float* qkv_w   = (const float*)d_in[3];
    const float* qkv_b   = (const float*)d_in[4];
    const float* proj_w  = (const float*)d_in[5];
    const float* proj_b  = (const float*)d_in[6];
    const float* n2g     = (const float*)d_in[7];
    const float* n2b     = (const float*)d_in[8];
    const float* fc1_w   = (const float*)d_in[9];
    const float* fc1_b   = (const float*)d_in[10];
    const float* fc2_w   = (const float*)d_in[11];
    const float* fc2_b   = (const float*)d_in[12];
    float* out = (float*)d_out;

    float *h1, *qkv, *scores, *olin, *x2, *h2, *h3;
    cudaGetSymbolAddress((void**)&h1,     g_h1);
    cudaGetSymbolAddress((void**)&qkv,    g_qkv);
    cudaGetSymbolAddress((void**)&scores, g_scores);
    cudaGetSymbolAddress((void**)&olin,   g_olin);
    cudaGetSymbolAddress((void**)&x2,     g_x2);
    cudaGetSymbolAddress((void**)&h2,     g_h2);
    cudaGetSymbolAddress((void**)&h3,     g_h3);

    // 1) LN1
    ln_kernel<<<TOK, 256>>>(x, n1g, n1b, h1);
    // 2) QKV = h1 @ qkv_w^T + b   [8192,2304]
    gemm_tn_kernel<EPI_BIAS><<<dim3(QKVDIM/128, TOK/128), 256>>>(
        h1, DIM, qkv_w, DIM, qkv, QKVDIM, DIM, qkv_b, nullptr, 0, 1.f);
    // 3) S = Q K^T * 0.125 per (b,h)
    gemm_qk_kernel<<<dim3(SEQ/128, SEQ/128, NBH), 256>>>(qkv, scores);
    // 4) softmax rows
    softmax_kernel<<<NBH * SEQ, 256>>>(scores);
    // 5) O = P @ V -> olin [8192,768]
    gemm_pv_kernel<<<dim3(1, SEQ/128, NBH), 256>>>(scores, qkv, olin);
    // 6) x2 = x + olin @ proj_w^T + b
    gemm_tn_kernel<EPI_BIAS_RES><<<dim3(DIM/128, TOK/128), 256>>>(
        olin, DIM, proj_w, DIM, x2, DIM, DIM, proj_b, x, DIM, 1.f);
    // 7) LN2
    ln_kernel<<<TOK, 256>>>(x2, n2g, n2b, h2);
    // 8) h3 = gelu(h2 @ fc1_w^T + b)
    gemm_tn_kernel<EPI_BIAS_GELU><<<dim3(HIDDEN/128, TOK/128), 256>>>(
        h2, DIM, fc1_w, DIM, h3, HIDDEN, DIM, fc1_b, nullptr, 0, 1.f);
    // 9) out = x2 + h3 @ fc2_w^T + b
    gemm_tn_kernel<EPI_BIAS_RES><<<dim3(DIM/128, TOK/128), 256>>>(
        h3, HIDDEN, fc2_w, HIDDEN, out, DIM, HIDDEN, fc2_b, x2, DIM, 1.f);
}

// round 2
// speedup vs baseline: 2.6060x; 2.6060x over previous
#include <cuda_runtime.h>
#include <math.h>

// Problem dims
#define DIM     768
#define HEADS   12
#define HD      64
#define HIDDEN  3072
#define SEQ     1024
#define BATCHN  8
#define TOK     (BATCHN*SEQ)   // 8192
#define QKVDIM  (3*DIM)        // 2304
#define NBH     (BATCHN*HEADS) // 96

#define APAD 20   // pad for [row][16k] smem tiles -> conflict-free frag loads
#define VPAD 72   // pad for PV's V tile [16k][64n]

// ---------------- scratch ----------------
__device__ float g_h1[TOK*DIM];
__device__ float g_qkv[(size_t)TOK*QKVDIM];
__device__ float g_scores[(size_t)NBH*SEQ*SEQ];
__device__ float g_olin[TOK*DIM];
__device__ float g_x2[TOK*DIM];
__device__ float g_h2[TOK*DIM];
__device__ float g_h3[(size_t)TOK*HIDDEN];

// ---------------- helpers ----------------
__device__ __forceinline__ unsigned f2tf(float x) {
    unsigned y; asm("cvt.rna.tf32.f32 %0, %1;" : "=r"(y) : "f"(x)); return y;
}
__device__ __forceinline__ void sts_tf32(float* dst, float4 v) {
    float4 o;
    o.x = __uint_as_float(f2tf(v.x));
    o.y = __uint_as_float(f2tf(v.y));
    o.z = __uint_as_float(f2tf(v.z));
    o.w = __uint_as_float(f2tf(v.w));
    *(float4*)dst = o;
}
__device__ __forceinline__ void mma8(float* d, const float* a, const float* b) {
    asm volatile(
        "mma.sync.aligned.m16n8k8.row.col.f32.tf32.tf32.f32 "
        "{%0,%1,%2,%3}, {%4,%5,%6,%7}, {%8,%9}, {%0,%1,%2,%3};"
        : "+f"(d[0]), "+f"(d[1]), "+f"(d[2]), "+f"(d[3])
        : "r"(__float_as_uint(a[0])), "r"(__float_as_uint(a[1])),
          "r"(__float_as_uint(a[2])), "r"(__float_as_uint(a[3])),
          "r"(__float_as_uint(b[0])), "r"(__float_as_uint(b[1])));
}
__device__ __forceinline__ float gelu1(float x) {
    return 0.5f * x * (1.f + erff(x * 0.70710678118654752f));
}

// ---------------- LayerNorm ----------------
__global__ void ln_kernel(const float* __restrict__ in,
                          const float* __restrict__ gam,
                          const float* __restrict__ bet,
                          float* __restrict__ out) {
    int row = blockIdx.x;
    int t = threadIdx.x;
    const float* x = in + (size_t)row * DIM;
    float v0 = x[t], v1 = x[t + 256], v2 = x[t + 512];
    float s  = v0 + v1 + v2;
    float sq = v0*v0 + v1*v1 + v2*v2;
    __shared__ float redS[8], redQ[8];
    #pragma unroll
    for (int o = 16; o > 0; o >>= 1) {
        s  += __shfl_xor_sync(0xffffffffu, s,  o);
        sq += __shfl_xor_sync(0xffffffffu, sq, o);
    }
    if ((t & 31) == 0) { redS[t >> 5] = s; redQ[t >> 5] = sq; }
    __syncthreads();
    if (t < 32) {
        float s2 = (t < 8) ? redS[t] : 0.f;
        float q2 = (t < 8) ? redQ[t] : 0.f;
        #pragma unroll
        for (int o = 4; o > 0; o >>= 1) {
            s2 += __shfl_xor_sync(0xffffffffu, s2, o);
            q2 += __shfl_xor_sync(0xffffffffu, q2, o);
        }
        if (t == 0) { redS[0] = s2; redQ[0] = q2; }
    }
    __syncthreads();
    float mu  = redS[0] * (1.0f / DIM);
    float var = redQ[0] * (1.0f / DIM) - mu * mu;
    float inv = rsqrtf(var + 1e-5f);
    float* o = out + (size_t)row * DIM;
    o[t]       = (v0 - mu) * inv * gam[t]       + bet[t];
    o[t + 256] = (v1 - mu) * inv * gam[t + 256] + bet[t + 256];
    o[t + 512] = (v2 - mu) * inv * gam[t + 512] + bet[t + 512];
}

// ---------------- TF32 MMA GEMM (TN): C[M,N] = A[M,K] @ W[N,K]^T ----------------
// 128x128x16 CTA tile, 8 warps of 64x32, m16n8k8 tf32 MMA, double-buffered smem.
enum { EPI_SCALE = 0, EPI_BIAS = 1, EPI_BIAS_RES = 2, EPI_BIAS_GELU = 3 };

template<int EPI>
__device__ __forceinline__ void mma_tn_body(
    const float* __restrict__ A, int lda,
    const float* __restrict__ W, int ldw,
    float* __restrict__ C, int ldc, int K,
    const float* __restrict__ bias,
    const float* __restrict__ res, int ldres,
    float alpha, int m0, int n0)
{
    __shared__ float As[2][128 * APAD];
    __shared__ float Ws[2][128 * APAD];

    const int tid  = threadIdx.x;
    const int lane = tid & 31;
    const int warp = tid >> 5;
    const int m0w  = (warp >> 2) * 64;
    const int n0w  = (warp & 3) * 32;
    const int gid  = lane >> 2;   // 0..7
    const int qid  = lane & 3;    // 0..3

    const int srow = tid >> 2;          // 0..63
    const int skc  = (tid & 3) * 4;     // 0,4,8,12

    const float* Ap  = A + (size_t)(m0 + srow) * lda + skc;
    const float* Ap2 = Ap + (size_t)64 * lda;
    const float* Wp  = W + (size_t)(n0 + srow) * ldw + skc;
    const float* Wp2 = Wp + (size_t)64 * ldw;

    float acc[4][4][4];
    #pragma unroll
    for (int i = 0; i < 4; i++)
        #pragma unroll
        for (int j = 0; j < 4; j++)
            #pragma unroll
            for (int r = 0; r < 4; r++) acc[i][j][r] = 0.f;

    // prologue: stage tile 0
    {
        float4 a0 = *(const float4*)(Ap);
        float4 a1 = *(const float4*)(Ap2);
        float4 w0 = *(const float4*)(Wp);
        float4 w1 = *(const float4*)(Wp2);
        sts_tf32(&As[0][srow * APAD + skc], a0);
        sts_tf32(&As[0][(srow + 64) * APAD + skc], a1);
        sts_tf32(&Ws[0][srow * APAD + skc], w0);
        sts_tf32(&Ws[0][(srow + 64) * APAD + skc], w1);
    }
    __syncthreads();

    const int nk = K / 16;
    for (int t = 0; t < nk; t++) {
        const int buf = t & 1;
        float4 a0, a1, w0, w1;
        const bool more = (t + 1 < nk);
        if (more) {
            int ko = (t + 1) * 16;
            a0 = *(const float4*)(Ap + ko);
            a1 = *(const float4*)(Ap2 + ko);
            w0 = *(const float4*)(Wp + ko);
            w1 = *(const float4*)(Wp2 + ko);
        }
        #pragma unroll
        for (int ks = 0; ks < 2; ks++) {
            const int c = ks * 8 + qid;
            float af[4][4], bf[4][2];
            #pragma unroll
            for (int mt = 0; mt < 4; mt++) {
                const float* p = &As[buf][(m0w + mt * 16 + gid) * APAD + c];
                af[mt][0] = p[0];
                af[mt][1] = p[8 * APAD];
                af[mt][2] = p[4];
                af[mt][3] = p[8 * APAD + 4];
            }
            #pragma unroll
            for (int nt = 0; nt < 4; nt++) {
                const float* p = &Ws[buf][(n0w + nt * 8 + gid) * APAD + c];
                bf[nt][0] = p[0];
                bf[nt][1] = p[4];
            }
            #pragma unroll
            for (int mt = 0; mt < 4; mt++)
                #pragma unroll
                for (int nt = 0; nt < 4; nt++)
                    mma8(acc[mt][nt], af[mt], bf[nt]);
        }
        if (more) {
            const int nb = buf ^ 1;
            sts_tf32(&As[nb][srow * APAD + skc], a0);
            sts_tf32(&As[nb][(srow + 64) * APAD + skc], a1);
            sts_tf32(&Ws[nb][srow * APAD + skc], w0);
            sts_tf32(&Ws[nb][(srow + 64) * APAD + skc], w1);
        }
        __syncthreads();
    }

    // epilogue
    #pragma unroll
    for (int mt = 0; mt < 4; mt++) {
        #pragma unroll
        for (int nt = 0; nt < 4; nt++) {
            int row = m0 + m0w + mt * 16 + gid;
            int col = n0 + n0w + nt * 8 + qid * 2;
            float2 v0, v1;
            v0.x = acc[mt][nt][0]; v0.y = acc[mt][nt][1];
            v1.x = acc[mt][nt][2]; v1.y = acc[mt][nt][3];
            if (EPI == EPI_SCALE) {
                v0.x *= alpha; v0.y *= alpha; v1.x *= alpha; v1.y *= alpha;
            }
            if (EPI >= EPI_BIAS) {
                float2 bb = *(const float2*)(bias + col);
                v0.x += bb.x; v0.y += bb.y; v1.x += bb.x; v1.y += bb.y;
            }
            if (EPI == EPI_BIAS_RES) {
                float2 r0 = *(const float2*)(res + (size_t)row * ldres + col);
                float2 r1 = *(const float2*)(res + (size_t)(row + 8) * ldres + col);
                v0.x += r0.x; v0.y += r0.y; v1.x += r1.x; v1.y += r1.y;
            }
            if (EPI == EPI_BIAS_GELU) {
                v0.x = gelu1(v0.x); v0.y = gelu1(v0.y);
                v1.x = gelu1(v1.x); v1.y = gelu1(v1.y);
            }
            *(float2*)(C + (size_t)row * ldc + col) = v0;
            *(float2*)(C + (size_t)(row + 8) * ldc + col) = v1;
        }
    }
}

template<int EPI>
__global__ __launch_bounds__(256)
void mma_tn_kernel(const float* __restrict__ A, int lda,
                   const float* __restrict__ W, int ldw,
                   float* __restrict__ C, int ldc, int K,
                   const float* __restrict__ bias,
                   const float* __restrict__ res, int ldres, float alpha) {
    mma_tn_body<EPI>(A, lda, W, ldw, C, ldc, K, bias, res, ldres, alpha,
                     blockIdx.y * 128, blockIdx.x * 128);
}

// S = (Q @ K^T) * scale per (b,h)
__global__ __launch_bounds__(256)
void qk_mma_kernel(const float* __restrict__ qkv, float* __restrict__ scores) {
    int z = blockIdx.z; int b = z / HEADS, h = z % HEADS;
    const float* Q  = qkv + (size_t)b * SEQ * QKVDIM + h * HD;
    const float* Kp = qkv + (size_t)b * SEQ * QKVDIM + DIM + h * HD;
    float* S = scores + (size_t)z * SEQ * SEQ;
    mma_tn_body<EPI_SCALE>(Q, QKVDIM, Kp, QKVDIM, S, SEQ, HD,
                           nullptr, nullptr, 0, 0.125f,
                           blockIdx.y * 128, blockIdx.x * 128);
}

// ---------------- softmax over rows of 1024 ----------------
__global__ __launch_bounds__(256)
void softmax_kernel(float* __restrict__ scores) {
    size_t row = blockIdx.x;
    float4* rp = (float4*)(scores + row * SEQ);
    int t = threadIdx.x;
    float4 v = rp[t];
    float mx = fmaxf(fmaxf(v.x, v.y), fmaxf(v.z, v.w));
    __shared__ float redM[8], redS[8];
    #pragma unroll
    for (int o = 16; o > 0; o >>= 1) mx = fmaxf(mx, __shfl_xor_sync(0xffffffffu, mx, o));
    if ((t & 31) == 0) redM[t >> 5] = mx;
    __syncthreads();
    if (t < 32) {
        float m2 = (t < 8) ? redM[t] : -1e30f;
        #pragma unroll
        for (int o = 4; o > 0; o >>= 1) m2 = fmaxf(m2, __shfl_xor_sync(0xffffffffu, m2, o));
        if (t == 0) redM[0] = m2;
    }
    __syncthreads();
    mx = redM[0];
    v.x = expf(v.x - mx); v.y = expf(v.y - mx);
    v.z = expf(v.z - mx); v.w = expf(v.w - mx);
    float s = v.x + v.y + v.z + v.w;
    #pragma unroll
    for (int o = 16; o > 0; o >>= 1) s += __shfl_xor_sync(0xffffffffu, s, o);
    if ((t & 31) == 0) redS[t >> 5] = s;
    __syncthreads();
    if (t < 32) {
        float s2 = (t < 8) ? redS[t] : 0.f;
        #pragma unroll
        for (int o = 4; o > 0; o >>= 1) s2 += __shfl_xor_sync(0xffffffffu, s2, o);
        if (t == 0) redS[0] = s2;
    }
    __syncthreads();
    float inv = 1.f / redS[0];
    v.x *= inv; v.y *= inv; v.z *= inv; v.w *= inv;
    rp[t] = v;
}

// ---------------- O = P @ V (NN, 128x64 tile, tf32 MMA) ----------------
__global__ __launch_bounds__(256)
void pv_mma_kernel(const float* __restrict__ scores,
                   const float* __restrict__ qkv,
                   float* __restrict__ olin) {
    int z = blockIdx.z; int b = z / HEADS, h = z % HEADS;
    const float* A = scores + (size_t)z * SEQ * SEQ;
    const float* V = qkv + (size_t)b * SEQ * QKVDIM + 2 * DIM + h * HD;
    float* C = olin + (size_t)b * SEQ * DIM + h * HD;
    const int m0 = blockIdx.y * 128;

    __shared__ float As[2][128 * APAD];
    __shared__ float Vs[2][16 * VPAD];

    const int tid  = threadIdx.x;
    const int lane = tid & 31;
    const int warp = tid >> 5;
    const int m0w  = (warp >> 1) * 32;   // 4 warps along M
    const int n0w  = (warp & 1) * 32;    // 2 warps along N
    const int gid  = lane >> 2;
    const int qid  = lane & 3;

    const int srow = tid >> 2;
    const int skc  = (tid & 3) * 4;
    const int vk   = tid >> 4;          // 0..15
    const int vn   = (tid & 15) * 4;    // 0..60

    const float* Ap  = A + (size_t)(m0 + srow) * SEQ + skc;
    const float* Ap2 = Ap + (size_t)64 * SEQ;
    const float* Vp  = V + (size_t)vk * QKVDIM + vn;

    float acc[2][4][4];
    #pragma unroll
    for (int i = 0; i < 2; i++)
        #pragma unroll
        for (int j = 0; j < 4; j++)
            #pragma unroll
            for (int r = 0; r < 4; r++) acc[i][j][r] = 0.f;

    {
        float4 a0 = *(const float4*)(Ap);
        float4 a1 = *(const float4*)(Ap2);
        float4 vv = *(const float4*)(Vp);
        sts_tf32(&As[0][srow * APAD + skc], a0);
        sts_tf32(&As[0][(srow + 64) * APAD + skc], a1);
        sts_tf32(&Vs[0][vk * VPAD + vn], vv);
    }
    __syncthreads();

    const int nk = SEQ / 16;   // 64
    for (int t = 0; t < nk; t++) {
        const int buf = t & 1;
        float4 a0, a1, vv;
        const bool more = (t + 1 < nk);
        if (more) {
            int ko = (t + 1) * 16;
            a0 = *(const float4*)(Ap + ko);
            a1 = *(const float4*)(Ap2 + ko);
            vv = *(const float4*)(Vp + (size_t)ko * QKVDIM);
        }
        #pragma unroll
        for (int ks = 0; ks < 2; ks++) {
            const int c = ks * 8 + qid;
            float af[2][4], bf[4][2];
            #pragma unroll
            for (int mt = 0; mt < 2; mt++) {
                const float* p = &As[buf][(m0w + mt * 16 + gid) * APAD + c];
                af[mt][0] = p[0];
                af[mt][1] = p[8 * APAD];
                af[mt][2] = p[4];
                af[mt][3] = p[8 * APAD + 4];
            }
            #pragma unroll
            for (int nt = 0; nt < 4; nt++) {
                const float* p = &Vs[buf][c * VPAD + n0w + nt * 8 + gid];
                bf[nt][0] = p[0];
                bf[nt][1] = p[4 * VPAD];
            }
            #pragma unroll
            for (int mt = 0; mt < 2; mt++)
                #pragma unroll
                for (int nt = 0; nt < 4; nt++)
                    mma8(acc[mt][nt], af[mt], bf[nt]);
        }
        if (more) {
            const int nb = buf ^ 1;
            sts_tf32(&As[nb][srow * APAD + skc], a0);
            sts_tf32(&As[nb][(srow + 64) * APAD + skc], a1);
            sts_tf32(&Vs[nb][vk * VPAD + vn], vv);
        }
        __syncthreads();
    }

    #pragma unroll
    for (int mt = 0; mt < 2; mt++) {
        #pragma unroll
        for (int nt = 0; nt < 4; nt++) {
            int row = m0 + m0w + mt * 16 + gid;
            int col = n0w + nt * 8 + qid * 2;
            float2 v0, v1;
            v0.x = acc[mt][nt][0]; v0.y = acc[mt][nt][1];
            v1.x = acc[mt][nt][2]; v1.y = acc[mt][nt][3];
            *(float2*)(C + (size_t)row * DIM + col) = v0;
            *(float2*)(C + (size_t)(row + 8) * DIM + col) = v1;
        }
    }
}

// ---------------- launch ----------------
extern "C" void kernel_launch(void* const* d_in, const int* in_sizes, int n_in,
                              void* d_out, int out_size) {
    const float* x       = (const float*)d_in[0];
    const float* n1g     = (const float*)d_in[1];
    const float* n1b     = (const float*)d_in[2];
    const float* qkv_w   = (const float*)d_in[3];
    const float* qkv_b   = (const float*)d_in[4];
    const float* proj_w  = (const float*)d_in[5];
    const float* proj_b  = (const float*)d_in[6];
    const float* n2g     = (const float*)d_in[7];
    const float* n2b     = (const float*)d_in[8];
    const float* fc1_w   = (const float*)d_in[9];
    const float* fc1_b   = (const float*)d_in[10];
    const float* fc2_w   = (const float*)d_in[11];
    const float* fc2_b   = (const float*)d_in[12];
    float* out = (float*)d_out;

    float *h1, *qkv, *scores, *olin, *x2, *h2, *h3;
    cudaGetSymbolAddress((void**)&h1,     g_h1);
    cudaGetSymbolAddress((void**)&qkv,    g_qkv);
    cudaGetSymbolAddress((void**)&scores, g_scores);
    cudaGetSymbolAddress((void**)&olin,   g_olin);
    cudaGetSymbolAddress((void**)&x2,     g_x2);
    cudaGetSymbolAddress((void**)&h2,     g_h2);
    cudaGetSymbolAddress((void**)&h3,     g_h3);

    // 1) LN1
    ln_kernel<<<TOK, 256>>>(x, n1g, n1b, h1);
    // 2) QKV = h1 @ qkv_w^T + b
    mma_tn_kernel<EPI_BIAS><<<dim3(QKVDIM/128, TOK/128), 256>>>(
        h1, DIM, qkv_w, DIM, qkv, QKVDIM, DIM, qkv_b, nullptr, 0, 1.f);
    // 3) S = Q K^T * 0.125
    qk_mma_kernel<<<dim3(SEQ/128, SEQ/128, NBH), 256>>>(qkv, scores);
    // 4) softmax
    softmax_kernel<<<NBH * SEQ, 256>>>(scores);
    // 5) O = P @ V
    pv_mma_kernel<<<dim3(1, SEQ/128, NBH), 256>>>(scores, qkv, olin);
    // 6) x2 = x + olin @ proj_w^T + b
    mma_tn_kernel<EPI_BIAS_RES><<<dim3(DIM/128, TOK/128), 256>>>(
        olin, DIM, proj_w, DIM, x2, DIM, DIM, proj_b, x, DIM, 1.f);
    // 7) LN2
    ln_kernel<<<TOK, 256>>>(x2, n2g, n2b, h2);
    // 8) h3 = gelu(h2 @ fc1_w^T + b)
    mma_tn_kernel<EPI_BIAS_GELU><<<dim3(HIDDEN/128, TOK/128), 256>>>(
        h2, DIM, fc1_w, DIM, h3, HIDDEN, DIM, fc1_b, nullptr, 0, 1.f);
    // 9) out = x2 + h3 @ fc2_w^T + b
    mma_tn_kernel<EPI_BIAS_RES><<<dim3(DIM/128, TOK/128), 256>>>(
        h3, HIDDEN, fc2_w, HIDDEN, out, DIM, HIDDEN, fc2_b, x2, DIM, 1.f);
}

// round 3
// speedup vs baseline: 2.9830x; 1.1447x over previous
#include <cuda_runtime.h>
#include <math.h>

// Problem dims
#define DIM     768
#define HEADS   12
#define HD      64
#define HIDDEN  3072
#define SEQ     1024
#define BATCHN  8
#define TOK     (BATCHN*SEQ)   // 8192
#define QKVDIM  (3*DIM)        // 2304
#define NBH     (BATCHN*HEADS) // 96

#define APAD 20

// flash smem strides (floats)
#define QK_STRIDE 68   // 64 + 4 : g*4+q distinct banks
#define V_STRIDE  72   // 64 + 8 : q*8+g distinct banks
#define P_STRIDE  132  // 128 + 4: g*4+q distinct banks

// ---------------- scratch ----------------
__device__ float g_h1[TOK*DIM];
__device__ float g_qkv[(size_t)TOK*QKVDIM];
__device__ float g_olin[TOK*DIM];
__device__ float g_x2[TOK*DIM];
__device__ float g_h2[TOK*DIM];
__device__ float g_h3[(size_t)TOK*HIDDEN];

// ---------------- helpers ----------------
__device__ __forceinline__ unsigned f2tf(float x) {
    unsigned y; asm("cvt.rna.tf32.f32 %0, %1;" : "=r"(y) : "f"(x)); return y;
}
__device__ __forceinline__ float tf32f(float x) { return __uint_as_float(f2tf(x)); }
__device__ __forceinline__ void sts_tf32(float* dst, float4 v) {
    float4 o;
    o.x = tf32f(v.x); o.y = tf32f(v.y); o.z = tf32f(v.z); o.w = tf32f(v.w);
    *(float4*)dst = o;
}
__device__ __forceinline__ void mma8(float* d, const float* a, const float* b) {
    asm volatile(
        "mma.sync.aligned.m16n8k8.row.col.f32.tf32.tf32.f32 "
        "{%0,%1,%2,%3}, {%4,%5,%6,%7}, {%8,%9}, {%0,%1,%2,%3};"
        : "+f"(d[0]), "+f"(d[1]), "+f"(d[2]), "+f"(d[3])
        : "r"(__float_as_uint(a[0])), "r"(__float_as_uint(a[1])),
          "r"(__float_as_uint(a[2])), "r"(__float_as_uint(a[3])),
          "r"(__float_as_uint(b[0])), "r"(__float_as_uint(b[1])));
}
__device__ __forceinline__ float gelu1(float x) {
    return 0.5f * x * (1.f + erff(x * 0.70710678118654752f));
}

// ---------------- LayerNorm ----------------
__global__ void ln_kernel(const float* __restrict__ in,
                          const float* __restrict__ gam,
                          const float* __restrict__ bet,
                          float* __restrict__ out) {
    int row = blockIdx.x;
    int t = threadIdx.x;
    const float* x = in + (size_t)row * DIM;
    float v0 = x[t], v1 = x[t + 256], v2 = x[t + 512];
    float s  = v0 + v1 + v2;
    float sq = v0*v0 + v1*v1 + v2*v2;
    __shared__ float redS[8], redQ[8];
    #pragma unroll
    for (int o = 16; o > 0; o >>= 1) {
        s  += __shfl_xor_sync(0xffffffffu, s,  o);
        sq += __shfl_xor_sync(0xffffffffu, sq, o);
    }
    if ((t & 31) == 0) { redS[t >> 5] = s; redQ[t >> 5] = sq; }
    __syncthreads();
    if (t < 32) {
        float s2 = (t < 8) ? redS[t] : 0.f;
        float q2 = (t < 8) ? redQ[t] : 0.f;
        #pragma unroll
        for (int o = 4; o > 0; o >>= 1) {
            s2 += __shfl_xor_sync(0xffffffffu, s2, o);
            q2 += __shfl_xor_sync(0xffffffffu, q2, o);
        }
        if (t == 0) { redS[0] = s2; redQ[0] = q2; }
    }
    __syncthreads();
    float mu  = redS[0] * (1.0f / DIM);
    float var = redQ[0] * (1.0f / DIM) - mu * mu;
    float inv = rsqrtf(var + 1e-5f);
    float* o = out + (size_t)row * DIM;
    o[t]       = (v0 - mu) * inv * gam[t]       + bet[t];
    o[t + 256] = (v1 - mu) * inv * gam[t + 256] + bet[t + 256];
    o[t + 512] = (v2 - mu) * inv * gam[t + 512] + bet[t + 512];
}

// ---------------- TF32 MMA GEMM (TN) : unchanged from R2 ----------------
enum { EPI_SCALE = 0, EPI_BIAS = 1, EPI_BIAS_RES = 2, EPI_BIAS_GELU = 3 };

template<int EPI>
__global__ __launch_bounds__(256)
void mma_tn_kernel(const float* __restrict__ A, int lda,
                   const float* __restrict__ W, int ldw,
                   float* __restrict__ C, int ldc, int K,
                   const float* __restrict__ bias,
                   const float* __restrict__ res, int ldres, float alpha) {
    __shared__ float As[2][128 * APAD];
    __shared__ float Ws[2][128 * APAD];
    const int m0 = blockIdx.y * 128, n0 = blockIdx.x * 128;

    const int tid  = threadIdx.x;
    const int lane = tid & 31;
    const int warp = tid >> 5;
    const int m0w  = (warp >> 2) * 64;
    const int n0w  = (warp & 3) * 32;
    const int gid  = lane >> 2;
    const int qid  = lane & 3;

    const int srow = tid >> 2;
    const int skc  = (tid & 3) * 4;

    const float* Ap  = A + (size_t)(m0 + srow) * lda + skc;
    const float* Ap2 = Ap + (size_t)64 * lda;
    const float* Wp  = W + (size_t)(n0 + srow) * ldw + skc;
    const float* Wp2 = Wp + (size_t)64 * ldw;

    float acc[4][4][4];
    #pragma unroll
    for (int i = 0; i < 4; i++)
        #pragma unroll
        for (int j = 0; j < 4; j++)
            #pragma unroll
            for (int r = 0; r < 4; r++) acc[i][j][r] = 0.f;

    {
        float4 a0 = *(const float4*)(Ap);
        float4 a1 = *(const float4*)(Ap2);
        float4 w0 = *(const float4*)(Wp);
        float4 w1 = *(const float4*)(Wp2);
        sts_tf32(&As[0][srow * APAD + skc], a0);
        sts_tf32(&As[0][(srow + 64) * APAD + skc], a1);
        sts_tf32(&Ws[0][srow * APAD + skc], w0);
        sts_tf32(&Ws[0][(srow + 64) * APAD + skc], w1);
    }
    __syncthreads();

    const int nk = K / 16;
    for (int t = 0; t < nk; t++) {
        const int buf = t & 1;
        float4 a0, a1, w0, w1;
        const bool more = (t + 1 < nk);
        if (more) {
            int ko = (t + 1) * 16;
            a0 = *(const float4*)(Ap + ko);
            a1 = *(const float4*)(Ap2 + ko);
            w0 = *(const float4*)(Wp + ko);
            w1 = *(const float4*)(Wp2 + ko);
        }
        #pragma unroll
        for (int ks = 0; ks < 2; ks++) {
            const int c = ks * 8 + qid;
            float af[4][4], bf[4][2];
            #pragma unroll
            for (int mt = 0; mt < 4; mt++) {
                const float* p = &As[buf][(m0w + mt * 16 + gid) * APAD + c];
                af[mt][0] = p[0];
                af[mt][1] = p[8 * APAD];
                af[mt][2] = p[4];
                af[mt][3] = p[8 * APAD + 4];
            }
            #pragma unroll
            for (int nt = 0; nt < 4; nt++) {
                const float* p = &Ws[buf][(n0w + nt * 8 + gid) * APAD + c];
                bf[nt][0] = p[0];
                bf[nt][1] = p[4];
            }
            #pragma unroll
            for (int mt = 0; mt < 4; mt++)
                #pragma unroll
                for (int nt = 0; nt < 4; nt++)
                    mma8(acc[mt][nt], af[mt], bf[nt]);
        }
        if (more) {
            const int nb = buf ^ 1;
            sts_tf32(&As[nb][srow * APAD + skc], a0);
            sts_tf32(&As[nb][(srow + 64) * APAD + skc], a1);
            sts_tf32(&Ws[nb][srow * APAD + skc], w0);
            sts_tf32(&Ws[nb][(srow + 64) * APAD + skc], w1);
        }
        __syncthreads();
    }

    #pragma unroll
    for (int mt = 0; mt < 4; mt++) {
        #pragma unroll
        for (int nt = 0; nt < 4; nt++) {
            int row = m0 + m0w + mt * 16 + gid;
            int col = n0 + n0w + nt * 8 + qid * 2;
            float2 v0, v1;
            v0.x = acc[mt][nt][0]; v0.y = acc[mt][nt][1];
            v1.x = acc[mt][nt][2]; v1.y = acc[mt][nt][3];
            if (EPI == EPI_SCALE) {
                v0.x *= alpha; v0.y *= alpha; v1.x *= alpha; v1.y *= alpha;
            }
            if (EPI >= EPI_BIAS) {
                float2 bb = *(const float2*)(bias + col);
                v0.x += bb.x; v0.y += bb.y; v1.x += bb.x; v1.y += bb.y;
            }
            if (EPI == EPI_BIAS_RES) {
                float2 r0 = *(const float2*)(res + (size_t)row * ldres + col);
                float2 r1 = *(const float2*)(res + (size_t)(row + 8) * ldres + col);
                v0.x += r0.x; v0.y += r0.y; v1.x += r1.x; v1.y += r1.y;
            }
            if (EPI == EPI_BIAS_GELU) {
                v0.x = gelu1(v0.x); v0.y = gelu1(v0.y);
                v1.x = gelu1(v1.x); v1.y = gelu1(v1.y);
            }
            *(float2*)(C + (size_t)row * ldc + col) = v0;
            *(float2*)(C + (size_t)(row + 8) * ldc + col) = v1;
        }
    }
}

// ---------------- Flash attention: QK^T -> online softmax -> PV, fused ----------------
// Grid: (SEQ/128, NBH). Block: 256 (8 warps x 16 q-rows).
// K/V chunks of 128 keys staged in smem (tf32). P round-trips through
// warp-private smem to become the A-fragment of the PV mma.
#define FLASH_SMEM ((128*QK_STRIDE + 128*QK_STRIDE + 128*V_STRIDE + 8*16*P_STRIDE) * 4)

__global__ __launch_bounds__(256)
void flash_kernel(const float* __restrict__ qkv, float* __restrict__ olin) {
    extern __shared__ float sm[];
    float* Qs = sm;                           // 128 x QK_STRIDE
    float* Ks = Qs + 128 * QK_STRIDE;         // 128 x QK_STRIDE
    float* Vs = Ks + 128 * QK_STRIDE;         // 128 x V_STRIDE
    float* Ps = Vs + 128 * V_STRIDE;          // 8 warps x 16 x P_STRIDE

    const int bh = blockIdx.y;
    const int b = bh / HEADS, h = bh % HEADS;
    const int m0 = blockIdx.x * 128;
    const float* Qg = qkv + (size_t)b * SEQ * QKVDIM + h * HD;
    const float* Kg = Qg + DIM;
    const float* Vg = Qg + 2 * DIM;

    const int tid = threadIdx.x, lane = tid & 31, warp = tid >> 5;
    const int gid = lane >> 2, qid = lane & 3;

    // Load Q tile (pre-scaled by 1/8, tf32)
    #pragma unroll
    for (int i = 0; i < 8; i++) {
        int f = i * 256 + tid;              // 0..2047
        int r = f >> 4, c4 = (f & 15) * 4;
        float4 v = *(const float4*)(Qg + (size_t)(m0 + r) * QKVDIM + c4);
        v.x *= 0.125f; v.y *= 0.125f; v.z *= 0.125f; v.w *= 0.125f;
        sts_tf32(&Qs[r * QK_STRIDE + c4], v);
    }
    __syncthreads();

    // Preload Q A-fragments (warp's 16 rows, 8 k-steps)
    float qf[8][4];
    #pragma unroll
    for (int kk = 0; kk < 8; kk++) {
        const float* p = &Qs[(warp * 16 + gid) * QK_STRIDE + kk * 8 + qid];
        qf[kk][0] = p[0];
        qf[kk][1] = p[8 * QK_STRIDE];
        qf[kk][2] = p[4];
        qf[kk][3] = p[8 * QK_STRIDE + 4];
    }

    float m_i[2] = {-1e30f, -1e30f};
    float l_i[2] = {0.f, 0.f};
    float oacc[8][4];
    #pragma unroll
    for (int nt = 0; nt < 8; nt++)
        #pragma unroll
        for (int r = 0; r < 4; r++) oacc[nt][r] = 0.f;

    float* Pw = Ps + warp * 16 * P_STRIDE;

    for (int kc = 0; kc < 8; kc++) {
        __syncthreads();   // previous chunk's Ks/Vs reads done
        const float* Kc = Kg + (size_t)(kc * 128) * QKVDIM;
        const float* Vc = Vg + (size_t)(kc * 128) * QKVDIM;
        #pragma unroll
        for (int i = 0; i < 8; i++) {
            int f = i * 256 + tid;
            int r = f >> 4, c4 = (f & 15) * 4;
            float4 kv = *(const float4*)(Kc + (size_t)r * QKVDIM + c4);
            sts_tf32(&Ks[r * QK_STRIDE + c4], kv);
            float4 vv = *(const float4*)(Vc + (size_t)r * QKVDIM + c4);
            sts_tf32(&Vs[r * V_STRIDE + c4], vv);
        }
        __syncthreads();

        // S = Q K^T (scaled): 16 n-tiles of 8 keys
        float sacc[16][4];
        #pragma unroll
        for (int nt = 0; nt < 16; nt++)
            #pragma unroll
            for (int r = 0; r < 4; r++) sacc[nt][r] = 0.f;
        #pragma unroll
        for (int kk = 0; kk < 8; kk++) {
            #pragma unroll
            for (int nt = 0; nt < 16; nt++) {
                float bf[2];
                const float* p = &Ks[(nt * 8 + gid) * QK_STRIDE + kk * 8 + qid];
                bf[0] = p[0];
                bf[1] = p[4];
                mma8(sacc[nt], qf[kk], bf);
            }
        }

        // row max (rows gid and gid+8)
        float mx0 = -1e30f, mx1 = -1e30f;
        #pragma unroll
        for (int nt = 0; nt < 16; nt++) {
            mx0 = fmaxf(mx0, fmaxf(sacc[nt][0], sacc[nt][1]));
            mx1 = fmaxf(mx1, fmaxf(sacc[nt][2], sacc[nt][3]));
        }
        mx0 = fmaxf(mx0, __shfl_xor_sync(0xffffffffu, mx0, 1));
        mx0 = fmaxf(mx0, __shfl_xor_sync(0xffffffffu, mx0, 2));
        mx1 = fmaxf(mx1, __shfl_xor_sync(0xffffffffu, mx1, 1));
        mx1 = fmaxf(mx1, __shfl_xor_sync(0xffffffffu, mx1, 2));

        float mnew0 = fmaxf(m_i[0], mx0);
        float mnew1 = fmaxf(m_i[1], mx1);
        float f0 = __expf(m_i[0] - mnew0);
        float f1 = __expf(m_i[1] - mnew1);
        m_i[0] = mnew0; m_i[1] = mnew1;
        l_i[0] *= f0;   l_i[1] *= f1;
        #pragma unroll
        for (int nt = 0; nt < 8; nt++) {
            oacc[nt][0] *= f0; oacc[nt][1] *= f0;
            oacc[nt][2] *= f1; oacc[nt][3] *= f1;
        }

        // P = exp(S - m), store tf32 to warp-private smem; row sums
        float rs0 = 0.f, rs1 = 0.f;
        #pragma unroll
        for (int nt = 0; nt < 16; nt++) {
            float p0 = __expf(sacc[nt][0] - mnew0);
            float p1 = __expf(sacc[nt][1] - mnew0);
            float p2 = __expf(sacc[nt][2] - mnew1);
            float p3 = __expf(sacc[nt][3] - mnew1);
            rs0 += p0 + p1; rs1 += p2 + p3;
            float2 lo; lo.x = tf32f(p0); lo.y = tf32f(p1);
            float2 hi; hi.x = tf32f(p2); hi.y = tf32f(p3);
            *(float2*)&Pw[gid * P_STRIDE + nt * 8 + qid * 2] = lo;
            *(float2*)&Pw[(gid + 8) * P_STRIDE + nt * 8 + qid * 2] = hi;
        }
        rs0 += __shfl_xor_sync(0xffffffffu, rs0, 1);
        rs0 += __shfl_xor_sync(0xffffffffu, rs0, 2);
        rs1 += __shfl_xor_sync(0xffffffffu, rs1, 1);
        rs1 += __shfl_xor_sync(0xffffffffu, rs1, 2);
        l_i[0] += rs0; l_i[1] += rs1;

        __syncwarp();

        // O += P @ V : 16 k-steps x 8 n-tiles
        #pragma unroll
        for (int kk = 0; kk < 16; kk++) {
            float af[4];
            const float* p = &Pw[gid * P_STRIDE + kk * 8 + qid];
            af[0] = p[0];
            af[1] = p[8 * P_STRIDE];
            af[2] = p[4];
            af[3] = p[8 * P_STRIDE + 4];
            #pragma unroll
            for (int nt = 0; nt < 8; nt++) {
                float bf[2];
                bf[0] = Vs[(kk * 8 + qid) * V_STRIDE + nt * 8 + gid];
                bf[1] = Vs[(kk * 8 + qid + 4) * V_STRIDE + nt * 8 + gid];
                mma8(oacc[nt], af, bf);
            }
        }
        __syncwarp();
    }

    // epilogue: O /= l, write to olin[b*SEQ + row][h*HD + col]
    float inv0 = 1.f / l_i[0];
    float inv1 = 1.f / l_i[1];
    float* C = olin + (size_t)b * SEQ * DIM + h * HD;
    int row = m0 + warp * 16 + gid;
    #pragma unroll
    for (int nt = 0; nt < 8; nt++) {
        int col = nt * 8 + qid * 2;
        float2 v0, v1;
        v0.x = oacc[nt][0] * inv0; v0.y = oacc[nt][1] * inv0;
        v1.x = oacc[nt][2] * inv1; v1.y = oacc[nt][3] * inv1;
        *(float2*)(C + (size_t)row * DIM + col) = v0;
        *(float2*)(C + (size_t)(row + 8) * DIM + col) = v1;
    }
}

// ---------------- launch ----------------
extern "C" void kernel_launch(void* const* d_in, const int* in_sizes, int n_in,
                              void* d_out, int out_size) {
    const float* x       = (const float*)d_in[0];
    const float* n1g     = (const float*)d_in[1];
    const float* n1b     = (const float*)d_in[2];
    const float* qkv_w   = (const float*)d_in[3];
    const float* qkv_b   = (const float*)d_in[4];
    const float* proj_w  = (const float*)d_in[5];
    const float* proj_b  = (const float*)d_in[6];
    const float* n2g     = (const float*)d_in[7];
    const float* n2b     = (const float*)d_in[8];
    const float* fc1_w   = (const float*)d_in[9];
    const float* fc1_b   = (const float*)d_in[10];
    const float* fc2_w   = (const float*)d_in[11];
    const float* fc2_b   = (const float*)d_in[12];
    float* out = (float*)d_out;

    float *h1, *qkv, *olin, *x2, *h2, *h3;
    cudaGetSymbolAddress((void**)&h1,   g_h1);
    cudaGetSymbolAddress((void**)&qkv,  g_qkv);
    cudaGetSymbolAddress((void**)&olin, g_olin);
    cudaGetSymbolAddress((void**)&x2,   g_x2);
    cudaGetSymbolAddress((void**)&h2,   g_h2);
    cudaGetSymbolAddress((void**)&h3,   g_h3);

    cudaFuncSetAttribute(flash_kernel,
                         cudaFuncAttributeMaxDynamicSharedMemorySize, FLASH_SMEM);

    // 1) LN1
    ln_kernel<<<TOK, 256>>>(x, n1g, n1b, h1);
    // 2) QKV = h1 @ qkv_w^T + b
    mma_tn_kernel<EPI_BIAS><<<dim3(QKVDIM/128, TOK/128), 256>>>(
        h1, DIM, qkv_w, DIM, qkv, QKVDIM, DIM, qkv_b, nullptr, 0, 1.f);
    // 3) fused attention -> olin
    flash_kernel<<<dim3(SEQ/128, NBH), 256, FLASH_SMEM>>>(qkv, olin);
    // 4) x2 = x + olin @ proj_w^T + b
    mma_tn_kernel<EPI_BIAS_RES><<<dim3(DIM/128, TOK/128), 256>>>(
        olin, DIM, proj_w, DIM, x2, DIM, DIM, proj_b, x, DIM, 1.f);
    // 5) LN2
    ln_kernel<<<TOK, 256>>>(x2, n2g, n2b, h2);
    // 6) h3 = gelu(h2 @ fc1_w^T + b)
    mma_tn_kernel<EPI_BIAS_GELU><<<dim3(HIDDEN/128, TOK/128), 256>>>(
        h2, DIM, fc1_w, DIM, h3, HIDDEN, DIM, fc1_b, nullptr, 0, 1.f);
    // 7) out = x2 + h3 @ fc2_w^T + b
    mma_tn_kernel<EPI_BIAS_RES><<<dim3(DIM/128, TOK/128), 256>>>(
        h3, HIDDEN, fc2_w, HIDDEN, out, DIM, HIDDEN, fc2_b, x2, DIM, 1.f);
}

// round 4
// speedup vs baseline: 3.2875x; 1.1021x over previous
#include <cuda_runtime.h>
#include <math.h>

// Problem dims
#define DIM     768
#define HEADS   12
#define HD      64
#define HIDDEN  3072
#define SEQ     1024
#define BATCHN  8
#define TOK     (BATCHN*SEQ)   // 8192
#define QKVDIM  (3*DIM)        // 2304
#define NBH     (BATCHN*HEADS) // 96

#define APAD 20
#define STAGES 3
#define GEMM_SMEM (STAGES * 2 * 128 * APAD * 4)   // 61440 B

// flash smem strides (floats)
#define QK_STRIDE 68
#define V_STRIDE  72
#define P_STRIDE  132
#define FLASH_SMEM ((128*QK_STRIDE + 128*QK_STRIDE + 128*V_STRIDE + 8*16*P_STRIDE) * 4)

// ---------------- scratch ----------------
__device__ float g_h1[TOK*DIM];
__device__ float g_qkv[(size_t)TOK*QKVDIM];
__device__ float g_olin[TOK*DIM];
__device__ float g_x2[TOK*DIM];
__device__ float g_h2[TOK*DIM];
__device__ float g_h3[(size_t)TOK*HIDDEN];

// ---------------- helpers ----------------
__device__ __forceinline__ unsigned f2tf(float x) {
    unsigned y; asm("cvt.rna.tf32.f32 %0, %1;" : "=r"(y) : "f"(x)); return y;
}
__device__ __forceinline__ float tf32f(float x) { return __uint_as_float(f2tf(x)); }
__device__ __forceinline__ void sts_tf32(float* dst, float4 v) {
    float4 o;
    o.x = tf32f(v.x); o.y = tf32f(v.y); o.z = tf32f(v.z); o.w = tf32f(v.w);
    *(float4*)dst = o;
}
__device__ __forceinline__ void mma8(float* d, const float* a, const float* b) {
    asm volatile(
        "mma.sync.aligned.m16n8k8.row.col.f32.tf32.tf32.f32 "
        "{%0,%1,%2,%3}, {%4,%5,%6,%7}, {%8,%9}, {%0,%1,%2,%3};"
        : "+f"(d[0]), "+f"(d[1]), "+f"(d[2]), "+f"(d[3])
        : "r"(__float_as_uint(a[0])), "r"(__float_as_uint(a[1])),
          "r"(__float_as_uint(a[2])), "r"(__float_as_uint(a[3])),
          "r"(__float_as_uint(b[0])), "r"(__float_as_uint(b[1])));
}
__device__ __forceinline__ float gelu1(float x) {
    return 0.5f * x * (1.f + erff(x * 0.70710678118654752f));
}
__device__ __forceinline__ void cp16(float* dst, const float* src) {
    unsigned d = (unsigned)__cvta_generic_to_shared(dst);
    asm volatile("cp.async.cg.shared.global [%0], [%1], 16;\n" :: "r"(d), "l"(src));
}
__device__ __forceinline__ void cp_commit() {
    asm volatile("cp.async.commit_group;\n");
}
template<int N>
__device__ __forceinline__ void cp_wait() {
    asm volatile("cp.async.wait_group %0;\n" :: "n"(N));
}

// ---------------- LayerNorm ----------------
__global__ void ln_kernel(const float* __restrict__ in,
                          const float* __restrict__ gam,
                          const float* __restrict__ bet,
                          float* __restrict__ out) {
    int row = blockIdx.x;
    int t = threadIdx.x;
    const float* x = in + (size_t)row * DIM;
    float v0 = x[t], v1 = x[t + 256], v2 = x[t + 512];
    float s  = v0 + v1 + v2;
    float sq = v0*v0 + v1*v1 + v2*v2;
    __shared__ float redS[8], redQ[8];
    #pragma unroll
    for (int o = 16; o > 0; o >>= 1) {
        s  += __shfl_xor_sync(0xffffffffu, s,  o);
        sq += __shfl_xor_sync(0xffffffffu, sq, o);
    }
    if ((t & 31) == 0) { redS[t >> 5] = s; redQ[t >> 5] = sq; }
    __syncthreads();
    if (t < 32) {
        float s2 = (t < 8) ? redS[t] : 0.f;
        float q2 = (t < 8) ? redQ[t] : 0.f;
        #pragma unroll
        for (int o = 4; o > 0; o >>= 1) {
            s2 += __shfl_xor_sync(0xffffffffu, s2, o);
            q2 += __shfl_xor_sync(0xffffffffu, q2, o);
        }
        if (t == 0) { redS[0] = s2; redQ[0] = q2; }
    }
    __syncthreads();
    float mu  = redS[0] * (1.0f / DIM);
    float var = redQ[0] * (1.0f / DIM) - mu * mu;
    float inv = rsqrtf(var + 1e-5f);
    float* o = out + (size_t)row * DIM;
    o[t]       = (v0 - mu) * inv * gam[t]       + bet[t];
    o[t + 256] = (v1 - mu) * inv * gam[t + 256] + bet[t + 256];
    o[t + 512] = (v2 - mu) * inv * gam[t + 512] + bet[t + 512];
}

// ---------------- TF32 MMA GEMM (TN), 3-stage cp.async pipeline ----------------
enum { EPI_BIAS = 1, EPI_BIAS_RES = 2, EPI_BIAS_GELU = 3 };

template<int EPI>
__global__ __launch_bounds__(256)
void mma_tn_kernel(const float* __restrict__ A, int lda,
                   const float* __restrict__ W, int ldw,
                   float* __restrict__ C, int ldc, int K,
                   const float* __restrict__ bias,
                   const float* __restrict__ res, int ldres) {
    extern __shared__ float smp[];
    float* AsBase = smp;                               // STAGES x 128*APAD
    float* WsBase = smp + STAGES * 128 * APAD;

    const int m0 = blockIdx.y * 128, n0 = blockIdx.x * 128;
    const int tid  = threadIdx.x;
    const int lane = tid & 31;
    const int warp = tid >> 5;
    const int m0w  = (warp >> 2) * 64;
    const int n0w  = (warp & 3) * 32;
    const int gid  = lane >> 2;
    const int qid  = lane & 3;

    const int srow = tid >> 2;          // 0..63
    const int skc  = (tid & 3) * 4;     // 0,4,8,12

    const float* Ap  = A + (size_t)(m0 + srow) * lda + skc;
    const float* Ap2 = Ap + (size_t)64 * lda;
    const float* Wp  = W + (size_t)(n0 + srow) * ldw + skc;
    const float* Wp2 = Wp + (size_t)64 * ldw;

    float acc[4][4][4];
    #pragma unroll
    for (int i = 0; i < 4; i++)
        #pragma unroll
        for (int j = 0; j < 4; j++)
            #pragma unroll
            for (int r = 0; r < 4; r++) acc[i][j][r] = 0.f;

    const int nk = K / 16;

    // prologue: stages 0,1
    #pragma unroll
    for (int s = 0; s < 2; s++) {
        float* as = AsBase + s * 128 * APAD;
        float* ws = WsBase + s * 128 * APAD;
        int ko = s * 16;
        cp16(&as[srow * APAD + skc], Ap + ko);
        cp16(&as[(srow + 64) * APAD + skc], Ap2 + ko);
        cp16(&ws[srow * APAD + skc], Wp + ko);
        cp16(&ws[(srow + 64) * APAD + skc], Wp2 + ko);
        cp_commit();
    }

    int buf = 0, nxt = 2;
    for (int t = 0; t < nk; t++) {
        cp_wait<1>();          // stage t landed
        __syncthreads();       // all threads past compute(t-1); safe to refill buf (t+2)%3

        if (t + 2 < nk) {
            float* as = AsBase + nxt * 128 * APAD;
            float* ws = WsBase + nxt * 128 * APAD;
            int ko = (t + 2) * 16;
            cp16(&as[srow * APAD + skc], Ap + ko);
            cp16(&as[(srow + 64) * APAD + skc], Ap2 + ko);
            cp16(&ws[srow * APAD + skc], Wp + ko);
            cp16(&ws[(srow + 64) * APAD + skc], Wp2 + ko);
        }
        cp_commit();           // commit (possibly empty) to keep group accounting

        const float* As = AsBase + buf * 128 * APAD;
        const float* Ws = WsBase + buf * 128 * APAD;
        #pragma unroll
        for (int ks = 0; ks < 2; ks++) {
            const int c = ks * 8 + qid;
            float af[4][4], bf[4][2];
            #pragma unroll
            for (int mt = 0; mt < 4; mt++) {
                const float* p = &As[(m0w + mt * 16 + gid) * APAD + c];
                af[mt][0] = p[0];
                af[mt][1] = p[8 * APAD];
                af[mt][2] = p[4];
                af[mt][3] = p[8 * APAD + 4];
            }
            #pragma unroll
            for (int nt = 0; nt < 4; nt++) {
                const float* p = &Ws[(n0w + nt * 8 + gid) * APAD + c];
                bf[nt][0] = p[0];
                bf[nt][1] = p[4];
            }
            #pragma unroll
            for (int mt = 0; mt < 4; mt++)
                #pragma unroll
                for (int nt = 0; nt < 4; nt++)
                    mma8(acc[mt][nt], af[mt], bf[nt]);
        }
        buf = (buf == 2) ? 0 : buf + 1;
        nxt = (nxt == 2) ? 0 : nxt + 1;
    }

    // epilogue
    #pragma unroll
    for (int mt = 0; mt < 4; mt++) {
        #pragma unroll
        for (int nt = 0; nt < 4; nt++) {
            int row = m0 + m0w + mt * 16 + gid;
            int col = n0 + n0w + nt * 8 + qid * 2;
            float2 v0, v1;
            v0.x = acc[mt][nt][0]; v0.y = acc[mt][nt][1];
            v1.x = acc[mt][nt][2]; v1.y = acc[mt][nt][3];
            {
                float2 bb = *(const float2*)(bias + col);
                v0.x += bb.x; v0.y += bb.y; v1.x += bb.x; v1.y += bb.y;
            }
            if (EPI == EPI_BIAS_RES) {
                float2 r0 = *(const float2*)(res + (size_t)row * ldres + col);
                float2 r1 = *(const float2*)(res + (size_t)(row + 8) * ldres + col);
                v0.x += r0.x; v0.y += r0.y; v1.x += r1.x; v1.y += r1.y;
            }
            if (EPI == EPI_BIAS_GELU) {
                v0.x = gelu1(v0.x); v0.y = gelu1(v0.y);
                v1.x = gelu1(v1.x); v1.y = gelu1(v1.y);
            }
            *(float2*)(C + (size_t)row * ldc + col) = v0;
            *(float2*)(C + (size_t)(row + 8) * ldc + col) = v1;
        }
    }
}

// ---------------- Flash attention (unchanged from R3) ----------------
__global__ __launch_bounds__(256)
void flash_kernel(const float* __restrict__ qkv, float* __restrict__ olin) {
    extern __shared__ float sm[];
    float* Qs = sm;
    float* Ks = Qs + 128 * QK_STRIDE;
    float* Vs = Ks + 128 * QK_STRIDE;
    float* Ps = Vs + 128 * V_STRIDE;

    const int bh = blockIdx.y;
    const int b = bh / HEADS, h = bh % HEADS;
    const int m0 = blockIdx.x * 128;
    const float* Qg = qkv + (size_t)b * SEQ * QKVDIM + h * HD;
    const float* Kg = Qg + DIM;
    const float* Vg = Qg + 2 * DIM;

    const int tid = threadIdx.x, lane = tid & 31, warp = tid >> 5;
    const int gid = lane >> 2, qid = lane & 3;

    #pragma unroll
    for (int i = 0; i < 8; i++) {
        int f = i * 256 + tid;
        int r = f >> 4, c4 = (f & 15) * 4;
        float4 v = *(const float4*)(Qg + (size_t)(m0 + r) * QKVDIM + c4);
        v.x *= 0.125f; v.y *= 0.125f; v.z *= 0.125f; v.w *= 0.125f;
        sts_tf32(&Qs[r * QK_STRIDE + c4], v);
    }
    __syncthreads();

    float qf[8][4];
    #pragma unroll
    for (int kk = 0; kk < 8; kk++) {
        const float* p = &Qs[(warp * 16 + gid) * QK_STRIDE + kk * 8 + qid];
        qf[kk][0] = p[0];
        qf[kk][1] = p[8 * QK_STRIDE];
        qf[kk][2] = p[4];
        qf[kk][3] = p[8 * QK_STRIDE + 4];
    }

    float m_i[2] = {-1e30f, -1e30f};
    float l_i[2] = {0.f, 0.f};
    float oacc[8][4];
    #pragma unroll
    for (int nt = 0; nt < 8; nt++)
        #pragma unroll
        for (int r = 0; r < 4; r++) oacc[nt][r] = 0.f;

    float* Pw = Ps + warp * 16 * P_STRIDE;

    for (int kc = 0; kc < 8; kc++) {
        __syncthreads();
        const float* Kc = Kg + (size_t)(kc * 128) * QKVDIM;
        const float* Vc = Vg + (size_t)(kc * 128) * QKVDIM;
        #pragma unroll
        for (int i = 0; i < 8; i++) {
            int f = i * 256 + tid;
            int r = f >> 4, c4 = (f & 15) * 4;
            float4 kv = *(const float4*)(Kc + (size_t)r * QKVDIM + c4);
            sts_tf32(&Ks[r * QK_STRIDE + c4], kv);
            float4 vv = *(const float4*)(Vc + (size_t)r * QKVDIM + c4);
            sts_tf32(&Vs[r * V_STRIDE + c4], vv);
        }
        __syncthreads();

        float sacc[16][4];
        #pragma unroll
        for (int nt = 0; nt < 16; nt++)
            #pragma unroll
            for (int r = 0; r < 4; r++) sacc[nt][r] = 0.f;
        #pragma unroll
        for (int kk = 0; kk < 8; kk++) {
            #pragma unroll
            for (int nt = 0; nt < 16; nt++) {
                float bf[2];
                const float* p = &Ks[(nt * 8 + gid) * QK_STRIDE + kk * 8 + qid];
                bf[0] = p[0];
                bf[1] = p[4];
                mma8(sacc[nt], qf[kk], bf);
            }
        }

        float mx0 = -1e30f, mx1 = -1e30f;
        #pragma unroll
        for (int nt = 0; nt < 16; nt++) {
            mx0 = fmaxf(mx0, fmaxf(sacc[nt][0], sacc[nt][1]));
            mx1 = fmaxf(mx1, fmaxf(sacc[nt][2], sacc[nt][3]));
        }
        mx0 = fmaxf(mx0, __shfl_xor_sync(0xffffffffu, mx0, 1));
        mx0 = fmaxf(mx0, __shfl_xor_sync(0xffffffffu, mx0, 2));
        mx1 = fmaxf(mx1, __shfl_xor_sync(0xffffffffu, mx1, 1));
        mx1 = fmaxf(mx1, __shfl_xor_sync(0xffffffffu, mx1, 2));

        float mnew0 = fmaxf(m_i[0], mx0);
        float mnew1 = fmaxf(m_i[1], mx1);
        float f0 = __expf(m_i[0] - mnew0);
        float f1 = __expf(m_i[1] - mnew1);
        m_i[0] = mnew0; m_i[1] = mnew1;
        l_i[0] *= f0;   l_i[1] *= f1;
        #pragma unroll
        for (int nt = 0; nt < 8; nt++) {
            oacc[nt][0] *= f0; oacc[nt][1] *= f0;
            oacc[nt][2] *= f1; oacc[nt][3] *= f1;
        }

        float rs0 = 0.f, rs1 = 0.f;
        #pragma unroll
        for (int nt = 0; nt < 16; nt++) {
            float p0 = __expf(sacc[nt][0] - mnew0);
            float p1 = __expf(sacc[nt][1] - mnew0);
            float p2 = __expf(sacc[nt][2] - mnew1);
            float p3 = __expf(sacc[nt][3] - mnew1);
            rs0 += p0 + p1; rs1 += p2 + p3;
            float2 lo; lo.x = tf32f(p0); lo.y = tf32f(p1);
            float2 hi; hi.x = tf32f(p2); hi.y = tf32f(p3);
            *(float2*)&Pw[gid * P_STRIDE + nt * 8 + qid * 2] = lo;
            *(float2*)&Pw[(gid + 8) * P_STRIDE + nt * 8 + qid * 2] = hi;
        }
        rs0 += __shfl_xor_sync(0xffffffffu, rs0, 1);
        rs0 += __shfl_xor_sync(0xffffffffu, rs0, 2);
        rs1 += __shfl_xor_sync(0xffffffffu, rs1, 1);
        rs1 += __shfl_xor_sync(0xffffffffu, rs1, 2);
        l_i[0] += rs0; l_i[1] += rs1;

        __syncwarp();

        #pragma unroll
        for (int kk = 0; kk < 16; kk++) {
            float af[4];
            const float* p = &Pw[gid * P_STRIDE + kk * 8 + qid];
            af[0] = p[0];
            af[1] = p[8 * P_STRIDE];
            af[2] = p[4];
            af[3] = p[8 * P_STRIDE + 4];
            #pragma unroll
            for (int nt = 0; nt < 8; nt++) {
                float bf[2];
                bf[0] = Vs[(kk * 8 + qid) * V_STRIDE + nt * 8 + gid];
                bf[1] = Vs[(kk * 8 + qid + 4) * V_STRIDE + nt * 8 + gid];
                mma8(oacc[nt], af, bf);
            }
        }
        __syncwarp();
    }

    float inv0 = 1.f / l_i[0];
    float inv1 = 1.f / l_i[1];
    float* C = olin + (size_t)b * SEQ * DIM + h * HD;
    int row = m0 + warp * 16 + gid;
    #pragma unroll
    for (int nt = 0; nt < 8; nt++) {
        int col = nt * 8 + qid * 2;
        float2 v0, v1;
        v0.x = oacc[nt][0] * inv0; v0.y = oacc[nt][1] * inv0;
        v1.x = oacc[nt][2] * inv1; v1.y = oacc[nt][3] * inv1;
        *(float2*)(C + (size_t)row * DIM + col) = v0;
        *(float2*)(C + (size_t)(row + 8) * DIM + col) = v1;
    }
}

// ---------------- launch ----------------
extern "C" void kernel_launch(void* const* d_in, const int* in_sizes, int n_in,
                              void* d_out, int out_size) {
    const float* x       = (const float*)d_in[0];
    const float* n1g     = (const float*)d_in[1];
    const float* n1b     = (const float*)d_in[2];
    const float* qkv_w   = (const float*)d_in[3];
    const float* qkv_b   = (const float*)d_in[4];
    const float* proj_w  = (const float*)d_in[5];
    const float* proj_b  = (const float*)d_in[6];
    const float* n2g     = (const float*)d_in[7];
    const float* n2b     = (const float*)d_in[8];
    const float* fc1_w   = (const float*)d_in[9];
    const float* fc1_b   = (const float*)d_in[10];
    const float* fc2_w   = (const float*)d_in[11];
    const float* fc2_b   = (const float*)d_in[12];
    float* out = (float*)d_out;

    float *h1, *qkv, *olin, *x2, *h2, *h3;
    cudaGetSymbolAddress((void**)&h1,   g_h1);
    cudaGetSymbolAddress((void**)&qkv,  g_qkv);
    cudaGetSymbolAddress((void**)&olin, g_olin);
    cudaGetSymbolAddress((void**)&x2,   g_x2);
    cudaGetSymbolAddress((void**)&h2,   g_h2);
    cudaGetSymbolAddress((void**)&h3,   g_h3);

    cudaFuncSetAttribute(mma_tn_kernel<EPI_BIAS>,
                         cudaFuncAttributeMaxDynamicSharedMemorySize, GEMM_SMEM);
    cudaFuncSetAttribute(mma_tn_kernel<EPI_BIAS_RES>,
                         cudaFuncAttributeMaxDynamicSharedMemorySize, GEMM_SMEM);
    cudaFuncSetAttribute(mma_tn_kernel<EPI_BIAS_GELU>,
                         cudaFuncAttributeMaxDynamicSharedMemorySize, GEMM_SMEM);
    cudaFuncSetAttribute(flash_kernel,
                         cudaFuncAttributeMaxDynamicSharedMemorySize, FLASH_SMEM);

    // 1) LN1
    ln_kernel<<<TOK, 256>>>(x, n1g, n1b, h1);
    // 2) QKV = h1 @ qkv_w^T + b
    mma_tn_kernel<EPI_BIAS><<<dim3(QKVDIM/128, TOK/128), 256, GEMM_SMEM>>>(
        h1, DIM, qkv_w, DIM, qkv, QKVDIM, DIM, qkv_b, nullptr, 0);
    // 3) fused attention -> olin
    flash_kernel<<<dim3(SEQ/128, NBH), 256, FLASH_SMEM>>>(qkv, olin);
    // 4) x2 = x + olin @ proj_w^T + b
    mma_tn_kernel<EPI_BIAS_RES><<<dim3(DIM/128, TOK/128), 256, GEMM_SMEM>>>(
        olin, DIM, proj_w, DIM, x2, DIM, DIM, proj_b, x, DIM);
    // 5) LN2
    ln_kernel<<<TOK, 256>>>(x2, n2g, n2b, h2);
    // 6) h3 = gelu(h2 @ fc1_w^T + b)
    mma_tn_kernel<EPI_BIAS_GELU><<<dim3(HIDDEN/128, TOK/128), 256, GEMM_SMEM>>>(
        h2, DIM, fc1_w, DIM, h3, HIDDEN, DIM, fc1_b, nullptr, 0);
    // 7) out = x2 + h3 @ fc2_w^T + b
    mma_tn_kernel<EPI_BIAS_RES><<<dim3(DIM/128, TOK/128), 256, GEMM_SMEM>>>(
        h3, HIDDEN, fc2_w, HIDDEN, out, DIM, HIDDEN, fc2_b, x2, DIM);
}

// round 6
// speedup vs baseline: 3.8189x; 1.1617x over previous
#include <cuda_runtime.h>
#include <math.h>
#include <stdint.h>

// Problem dims
#define DIM     768
#define HEADS   12
#define HD      64
#define HIDDEN  3072
#define SEQ     1024
#define BATCHN  8
#define TOK     (BATCHN*SEQ)   // 8192
#define QKVDIM  (3*DIM)        // 2304
#define NBH     (BATCHN*HEADS) // 96

// GEMM tiling
#define BK       32
#define KSTRIDE  36                       // 32 + 4 pad: bank = 4*gid + qid, all distinct
#define STAGE_F  (128 * KSTRIDE)          // floats per (A or W) stage
#define GEMM_SMEM (2 * 2 * STAGE_F * 4)   // 73728 B

// flash smem strides (floats)
#define QK_STRIDE 68
#define V_STRIDE  72
#define P_STRIDE  132
#define FLASH_SMEM ((128*QK_STRIDE + 128*QK_STRIDE + 128*V_STRIDE + 8*16*P_STRIDE) * 4)

// ---------------- scratch ----------------
__device__ float g_h1[TOK*DIM];
__device__ float g_qkv[(size_t)TOK*QKVDIM];
__device__ float g_olin[TOK*DIM];
__device__ float g_x2[TOK*DIM];
__device__ float g_h2[TOK*DIM];
__device__ float g_h3[(size_t)TOK*HIDDEN];

// ---------------- helpers ----------------
__device__ __forceinline__ unsigned f2tf(float x) {
    unsigned y; asm("cvt.rna.tf32.f32 %0, %1;" : "=r"(y) : "f"(x)); return y;
}
__device__ __forceinline__ float tf32f(float x) { return __uint_as_float(f2tf(x)); }
__device__ __forceinline__ void sts_tf32(float* dst, float4 v) {
    float4 o;
    o.x = tf32f(v.x); o.y = tf32f(v.y); o.z = tf32f(v.z); o.w = tf32f(v.w);
    *(float4*)dst = o;
}
__device__ __forceinline__ void mma8(float* d, const float* a, const float* b) {
    asm volatile(
        "mma.sync.aligned.m16n8k8.row.col.f32.tf32.tf32.f32 "
        "{%0,%1,%2,%3}, {%4,%5,%6,%7}, {%8,%9}, {%0,%1,%2,%3};"
        : "+f"(d[0]), "+f"(d[1]), "+f"(d[2]), "+f"(d[3])
        : "r"(__float_as_uint(a[0])), "r"(__float_as_uint(a[1])),
          "r"(__float_as_uint(a[2])), "r"(__float_as_uint(a[3])),
          "r"(__float_as_uint(b[0])), "r"(__float_as_uint(b[1])));
}
__device__ __forceinline__ float gelu1(float x) {
    return 0.5f * x * (1.f + erff(x * 0.70710678118654752f));
}
__device__ __forceinline__ void cp16(float* dst, const float* src) {
    unsigned d = (unsigned)__cvta_generic_to_shared(dst);
    asm volatile("cp.async.cg.shared.global [%0], [%1], 16;\n" :: "r"(d), "l"(src));
}
__device__ __forceinline__ void cp_commit() {
    asm volatile("cp.async.commit_group;\n");
}
template<int N>
__device__ __forceinline__ void cp_wait() {
    asm volatile("cp.async.wait_group %0;\n" :: "n"(N));
}

// ---------------- LayerNorm ----------------
__global__ void ln_kernel(const float* __restrict__ in,
                          const float* __restrict__ gam,
                          const float* __restrict__ bet,
                          float* __restrict__ out) {
    int row = blockIdx.x;
    int t = threadIdx.x;
    const float* x = in + (size_t)row * DIM;
    float v0 = x[t], v1 = x[t + 256], v2 = x[t + 512];
    float s  = v0 + v1 + v2;
    float sq = v0*v0 + v1*v1 + v2*v2;
    __shared__ float redS[8], redQ[8];
    #pragma unroll
    for (int o = 16; o > 0; o >>= 1) {
        s  += __shfl_xor_sync(0xffffffffu, s,  o);
        sq += __shfl_xor_sync(0xffffffffu, sq, o);
    }
    if ((t & 31) == 0) { redS[t >> 5] = s; redQ[t >> 5] = sq; }
    __syncthreads();
    if (t < 32) {
        float s2 = (t < 8) ? redS[t] : 0.f;
        float q2 = (t < 8) ? redQ[t] : 0.f;
        #pragma unroll
        for (int o = 4; o > 0; o >>= 1) {
            s2 += __shfl_xor_sync(0xffffffffu, s2, o);
            q2 += __shfl_xor_sync(0xffffffffu, q2, o);
        }
        if (t == 0) { redS[0] = s2; redQ[0] = q2; }
    }
    __syncthreads();
    float mu  = redS[0] * (1.0f / DIM);
    float var = redQ[0] * (1.0f / DIM) - mu * mu;
    float inv = rsqrtf(var + 1e-5f);
    float* o = out + (size_t)row * DIM;
    o[t]       = (v0 - mu) * inv * gam[t]       + bet[t];
    o[t + 256] = (v1 - mu) * inv * gam[t + 256] + bet[t + 256];
    o[t + 512] = (v2 - mu) * inv * gam[t + 512] + bet[t + 512];
}

// ---------------- TF32 MMA GEMM (TN), 128 thr, warp 64x64, 2-stage cp.async ----------
enum { EPI_BIAS = 1, EPI_BIAS_RES = 2, EPI_BIAS_GELU = 3 };

template<int EPI>
__global__ __launch_bounds__(128)
void mma_tn_kernel(const float* __restrict__ A, int lda,
                   const float* __restrict__ W, int ldw,
                   float* __restrict__ C, int ldc, int K,
                   const float* __restrict__ bias,
                   const float* __restrict__ res, int ldres) {
    extern __shared__ float smp[];
    // layout: [stage][A(128*36) | W(128*36)]
    const int m0 = blockIdx.y * 128, n0 = blockIdx.x * 128;
    const int tid  = threadIdx.x;
    const int lane = tid & 31;
    const int warp = tid >> 5;
    const int m0w  = (warp >> 1) * 64;   // 2 warps along M
    const int n0w  = (warp & 1) * 64;    // 2 warps along N
    const int gid  = lane >> 2;
    const int qid  = lane & 3;

    // cp.async mapping: 1024 16B-chunks per (A|W) stage, 128 threads -> 8 each
    const int crow0 = tid >> 3;          // 0..15 base row
    const int cgr   = tid & 7;           // 16B group within row (0..7)

    float acc[4][8][4];
    #pragma unroll
    for (int i = 0; i < 4; i++)
        #pragma unroll
        for (int j = 0; j < 8; j++)
            #pragma unroll
            for (int r = 0; r < 4; r++) acc[i][j][r] = 0.f;

    const int nch = K / BK;

    // stage loader
    auto load_chunk = [&](int j) {
        float* as = smp + (j & 1) * 2 * STAGE_F;
        float* ws = as + STAGE_F;
        const float* Aj = A + (size_t)m0 * lda + j * BK + cgr * 4;
        const float* Wj = W + (size_t)n0 * ldw + j * BK + cgr * 4;
        #pragma unroll
        for (int r = 0; r < 8; r++) {
            int row = crow0 + r * 16;
            cp16(&as[row * KSTRIDE + cgr * 4], Aj + (size_t)row * lda);
            cp16(&ws[row * KSTRIDE + cgr * 4], Wj + (size_t)row * ldw);
        }
    };

    load_chunk(0);
    cp_commit();

    for (int i = 0; i < nch; i++) {
        cp_wait<0>();
        __syncthreads();     // chunk i visible to all; all done reading buf (i+1)&1

        if (i + 1 < nch) {
            load_chunk(i + 1);
            cp_commit();
        }

        const float* As = smp + (i & 1) * 2 * STAGE_F;
        const float* Ws = As + STAGE_F;
        #pragma unroll
        for (int ks = 0; ks < 4; ks++) {
            const int c = ks * 8 + qid;
            float af[4][4], bf[8][2];
            #pragma unroll
            for (int mt = 0; mt < 4; mt++) {
                const float* p = &As[(m0w + mt * 16 + gid) * KSTRIDE + c];
                af[mt][0] = p[0];
                af[mt][1] = p[8 * KSTRIDE];
                af[mt][2] = p[4];
                af[mt][3] = p[8 * KSTRIDE + 4];
            }
            #pragma unroll
            for (int nt = 0; nt < 8; nt++) {
                const float* p = &Ws[(n0w + nt * 8 + gid) * KSTRIDE + c];
                bf[nt][0] = p[0];
                bf[nt][1] = p[4];
            }
            #pragma unroll
            for (int mt = 0; mt < 4; mt++)
                #pragma unroll
                for (int nt = 0; nt < 8; nt++)
                    mma8(acc[mt][nt], af[mt], bf[nt]);
        }
    }

    // epilogue
    #pragma unroll
    for (int mt = 0; mt < 4; mt++) {
        #pragma unroll
        for (int nt = 0; nt < 8; nt++) {
            int row = m0 + m0w + mt * 16 + gid;
            int col = n0 + n0w + nt * 8 + qid * 2;
            float2 v0, v1;
            v0.x = acc[mt][nt][0]; v0.y = acc[mt][nt][1];
            v1.x = acc[mt][nt][2]; v1.y = acc[mt][nt][3];
            {
                float2 bb = *(const float2*)(bias + col);
                v0.x += bb.x; v0.y += bb.y; v1.x += bb.x; v1.y += bb.y;
            }
            if (EPI == EPI_BIAS_RES) {
                float2 r0 = *(const float2*)(res + (size_t)row * ldres + col);
                float2 r1 = *(const float2*)(res + (size_t)(row + 8) * ldres + col);
                v0.x += r0.x; v0.y += r0.y; v1.x += r1.x; v1.y += r1.y;
            }
            if (EPI == EPI_BIAS_GELU) {
                v0.x = gelu1(v0.x); v0.y = gelu1(v0.y);
                v1.x = gelu1(v1.x); v1.y = gelu1(v1.y);
            }
            *(float2*)(C + (size_t)row * ldc + col) = v0;
            *(float2*)(C + (size_t)(row + 8) * ldc + col) = v1;
        }
    }
}

// ---------------- Flash attention (unchanged from R4) ----------------
__global__ __launch_bounds__(256)
void flash_kernel(const float* __restrict__ qkv, float* __restrict__ olin) {
    extern __shared__ float sm[];
    float* Qs = sm;
    float* Ks = Qs + 128 * QK_STRIDE;
    float* Vs = Ks + 128 * QK_STRIDE;
    float* Ps = Vs + 128 * V_STRIDE;

    const int bh = blockIdx.y;
    const int b = bh / HEADS, h = bh % HEADS;
    const int m0 = blockIdx.x * 128;
    const float* Qg = qkv + (size_t)b * SEQ * QKVDIM + h * HD;
    const float* Kg = Qg + DIM;
    const float* Vg = Qg + 2 * DIM;

    const int tid = threadIdx.x, lane = tid & 31, warp = tid >> 5;
    const int gid = lane >> 2, qid = lane & 3;

    #pragma unroll
    for (int i = 0; i < 8; i++) {
        int f = i * 256 + tid;
        int r = f >> 4, c4 = (f & 15) * 4;
        float4 v = *(const float4*)(Qg + (size_t)(m0 + r) * QKVDIM + c4);
        v.x *= 0.125f; v.y *= 0.125f; v.z *= 0.125f; v.w *= 0.125f;
        sts_tf32(&Qs[r * QK_STRIDE + c4], v);
    }
    __syncthreads();

    float qf[8][4];
    #pragma unroll
    for (int kk = 0; kk < 8; kk++) {
        const float* p = &Qs[(warp * 16 + gid) * QK_STRIDE + kk * 8 + qid];
        qf[kk][0] = p[0];
        qf[kk][1] = p[8 * QK_STRIDE];
        qf[kk][2] = p[4];
        qf[kk][3] = p[8 * QK_STRIDE + 4];
    }

    float m_i[2] = {-1e30f, -1e30f};
    float l_i[2] = {0.f, 0.f};
    float oacc[8][4];
    #pragma unroll
    for (int nt = 0; nt < 8; nt++)
        #pragma unroll
        for (int r = 0; r < 4; r++) oacc[nt][r] = 0.f;

    float* Pw = Ps + warp * 16 * P_STRIDE;

    for (int kc = 0; kc < 8; kc++) {
        __syncthreads();
        const float* Kc = Kg + (size_t)(kc * 128) * QKVDIM;
        const float* Vc = Vg + (size_t)(kc * 128) * QKVDIM;
        #pragma unroll
        for (int i = 0; i < 8; i++) {
            int f = i * 256 + tid;
            int r = f >> 4, c4 = (f & 15) * 4;
            float4 kv = *(const float4*)(Kc + (size_t)r * QKVDIM + c4);
            sts_tf32(&Ks[r * QK_STRIDE + c4], kv);
            float4 vv = *(const float4*)(Vc + (size_t)r * QKVDIM + c4);
            sts_tf32(&Vs[r * V_STRIDE + c4], vv);
        }
        __syncthreads();

        float sacc[16][4];
        #pragma unroll
        for (int nt = 0; nt < 16; nt++)
            #pragma unroll
            for (int r = 0; r < 4; r++) sacc[nt][r] = 0.f;
        #pragma unroll
        for (int kk = 0; kk < 8; kk++) {
            #pragma unroll
            for (int nt = 0; nt < 16; nt++) {
                float bf[2];
                const float* p = &Ks[(nt * 8 + gid) * QK_STRIDE + kk * 8 + qid];
                bf[0] = p[0];
                bf[1] = p[4];
                mma8(sacc[nt], qf[kk], bf);
            }
        }

        float mx0 = -1e30f, mx1 = -1e30f;
        #pragma unroll
        for (int nt = 0; nt < 16; nt++) {
            mx0 = fmaxf(mx0, fmaxf(sacc[nt][0], sacc[nt][1]));
            mx1 = fmaxf(mx1, fmaxf(sacc[nt][2], sacc[nt][3]));
        }
        mx0 = fmaxf(mx0, __shfl_xor_sync(0xffffffffu, mx0, 1));
        mx0 = fmaxf(mx0, __shfl_xor_sync(0xffffffffu, mx0, 2));
        mx1 = fmaxf(mx1, __shfl_xor_sync(0xffffffffu, mx1, 1));
        mx1 = fmaxf(mx1, __shfl_xor_sync(0xffffffffu, mx1, 2));

        float mnew0 = fmaxf(m_i[0], mx0);
        float mnew1 = fmaxf(m_i[1], mx1);
        float f0 = __expf(m_i[0] - mnew0);
        float f1 = __expf(m_i[1] - mnew1);
        m_i[0] = mnew0; m_i[1] = mnew1;
        l_i[0] *= f0;   l_i[1] *= f1;
        #pragma unroll
        for (int nt = 0; nt < 8; nt++) {
            oacc[nt][0] *= f0; oacc[nt][1] *= f0;
            oacc[nt][2] *= f1; oacc[nt][3] *= f1;
        }

        float rs0 = 0.f, rs1 = 0.f;
        #pragma unroll
        for (int nt = 0; nt < 16; nt++) {
            float p0 = __expf(sacc[nt][0] - mnew0);
            float p1 = __expf(sacc[nt][1] - mnew0);
            float p2 = __expf(sacc[nt][2] - mnew1);
            float p3 = __expf(sacc[nt][3] - mnew1);
            rs0 += p0 + p1; rs1 += p2 + p3;
            float2 lo; lo.x = tf32f(p0); lo.y = tf32f(p1);
            float2 hi; hi.x = tf32f(p2); hi.y = tf32f(p3);
            *(float2*)&Pw[gid * P_STRIDE + nt * 8 + qid * 2] = lo;
            *(float2*)&Pw[(gid + 8) * P_STRIDE + nt * 8 + qid * 2] = hi;
        }
        rs0 += __shfl_xor_sync(0xffffffffu, rs0, 1);
        rs0 += __shfl_xor_sync(0xffffffffu, rs0, 2);
        rs1 += __shfl_xor_sync(0xffffffffu, rs1, 1);
        rs1 += __shfl_xor_sync(0xffffffffu, rs1, 2);
        l_i[0] += rs0; l_i[1] += rs1;

        __syncwarp();

        #pragma unroll
        for (int kk = 0; kk < 16; kk++) {
            float af[4];
            const float* p = &Pw[gid * P_STRIDE + kk * 8 + qid];
            af[0] = p[0];
            af[1] = p[8 * P_STRIDE];
            af[2] = p[4];
            af[3] = p[8 * P_STRIDE + 4];
            #pragma unroll
            for (int nt = 0; nt < 8; nt++) {
                float bf[2];
                bf[0] = Vs[(kk * 8 + qid) * V_STRIDE + nt * 8 + gid];
                bf[1] = Vs[(kk * 8 + qid + 4) * V_STRIDE + nt * 8 + gid];
                mma8(oacc[nt], af, bf);
            }
        }
        __syncwarp();
    }

    float inv0 = 1.f / l_i[0];
    float inv1 = 1.f / l_i[1];
    float* C = olin + (size_t)b * SEQ * DIM + h * HD;
    int row = m0 + warp * 16 + gid;
    #pragma unroll
    for (int nt = 0; nt < 8; nt++) {
        int col = nt * 8 + qid * 2;
        float2 v0, v1;
        v0.x = oacc[nt][0] * inv0; v0.y = oacc[nt][1] * inv0;
        v1.x = oacc[nt][2] * inv1; v1.y = oacc[nt][3] * inv1;
        *(float2*)(C + (size_t)row * DIM + col) = v0;
        *(float2*)(C + (size_t)(row + 8) * DIM + col) = v1;
    }
}

// ---------------- launch ----------------
extern "C" void kernel_launch(void* const* d_in, const int* in_sizes, int n_in,
                              void* d_out, int out_size) {
    const float* x       = (const float*)d_in[0];
    const float* n1g     = (const float*)d_in[1];
    const float* n1b     = (const float*)d_in[2];
    const float* qkv_w   = (const float*)d_in[3];
    const float* qkv_b   = (const float*)d_in[4];
    const float* proj_w  = (const float*)d_in[5];
    const float* proj_b  = (const float*)d_in[6];
    const float* n2g     = (const float*)d_in[7];
    const float* n2b     = (const float*)d_in[8];
    const float* fc1_w   = (const float*)d_in[9];
    const float* fc1_b   = (const float*)d_in[10];
    const float* fc2_w   = (const float*)d_in[11];
    const float* fc2_b   = (const float*)d_in[12];
    float* out = (float*)d_out;

    float *h1, *qkv, *olin, *x2, *h2, *h3;
    cudaGetSymbolAddress((void**)&h1,   g_h1);
    cudaGetSymbolAddress((void**)&qkv,  g_qkv);
    cudaGetSymbolAddress((void**)&olin, g_olin);
    cudaGetSymbolAddress((void**)&x2,   g_x2);
    cudaGetSymbolAddress((void**)&h2,   g_h2);
    cudaGetSymbolAddress((void**)&h3,   g_h3);

    cudaFuncSetAttribute(mma_tn_kernel<EPI_BIAS>,
                         cudaFuncAttributeMaxDynamicSharedMemorySize, GEMM_SMEM);
    cudaFuncSetAttribute(mma_tn_kernel<EPI_BIAS_RES>,
                         cudaFuncAttributeMaxDynamicSharedMemorySize, GEMM_SMEM);
    cudaFuncSetAttribute(mma_tn_kernel<EPI_BIAS_GELU>,
                         cudaFuncAttributeMaxDynamicSharedMemorySize, GEMM_SMEM);
    cudaFuncSetAttribute(flash_kernel,
                         cudaFuncAttributeMaxDynamicSharedMemorySize, FLASH_SMEM);

    // 1) LN1
    ln_kernel<<<TOK, 256>>>(x, n1g, n1b, h1);
    // 2) QKV = h1 @ qkv_w^T + b
    mma_tn_kernel<EPI_BIAS><<<dim3(QKVDIM/128, TOK/128), 128, GEMM_SMEM>>>(
        h1, DIM, qkv_w, DIM, qkv, QKVDIM, DIM, qkv_b, nullptr, 0);
    // 3) fused attention -> olin
    flash_kernel<<<dim3(SEQ/128, NBH), 256, FLASH_SMEM>>>(qkv, olin);
    // 4) x2 = x + olin @ proj_w^T + b
    mma_tn_kernel<EPI_BIAS_RES><<<dim3(DIM/128, TOK/128), 128, GEMM_SMEM>>>(
        olin, DIM, proj_w, DIM, x2, DIM, DIM, proj_b, x, DIM);
    // 5) LN2
    ln_kernel<<<TOK, 256>>>(x2, n2g, n2b, h2);
    // 6) h3 = gelu(h2 @ fc1_w^T + b)
    mma_tn_kernel<EPI_BIAS_GELU><<<dim3(HIDDEN/128, TOK/128), 128, GEMM_SMEM>>>(
        h2, DIM, fc1_w, DIM, h3, HIDDEN, DIM, fc1_b, nullptr, 0);
    // 7) out = x2 + h3 @ fc2_w^T + b
    mma_tn_kernel<EPI_BIAS_RES><<<dim3(DIM/128, TOK/128), 128, GEMM_SMEM>>>(
        h3, HIDDEN, fc2_w, HIDDEN, out, DIM, HIDDEN, fc2_b, x2, DIM);
}